// round 7
// baseline (speedup 1.0000x reference)
#include <cuda_runtime.h>
#include <cuda_fp16.h>
#include <math.h>

#define N_NODES 50000
#define N_EDGES 800000
#define NFEAT 256
#define NHID 64
#define NCLASS 2
#define NB ((N_NODES + 255) / 256)   // 196 chunks of 256 nodes

typedef unsigned long long u64;

// ---------------- scratch (static device globals; no allocation) ----------------
__device__ int    g_deg_src[N_NODES];     // zero at load; re-zeroed by agg2 each call
__device__ int    g_deg_dst[N_NODES];
__device__ float  g_norm_src[N_NODES];
__device__ float  g_norm_dst[N_NODES];
__device__ int    g_blocksum[NB];         // per-256-node-chunk in-degree totals
__device__ int    g_offsets[N_NODES + 1];
__device__ int    g_cursor[N_NODES];
__device__ int    g_csr[N_EDGES];          // src node id, bucketed by dst
__device__ __half g_h [N_NODES * NHID];    // x @ W1 (unscaled), fp16
__device__ float  g_h2[N_NODES * NCLASS];  // per-node layer2 logits (pre-agg)
__device__ int    g_is64;

// ---------------- packed f32x2 helpers ----------------
__device__ __forceinline__ u64 fma_f32x2(u64 a, u64 b, u64 c) {
    u64 d;
    asm("fma.rn.f32x2 %0, %1, %2, %3;" : "=l"(d) : "l"(a), "l"(b), "l"(c));
    return d;
}
__device__ __forceinline__ u64 pack_f32x2(float lo, float hi) {
    u64 d;
    asm("mov.b64 %0, {%1, %2};" : "=l"(d) : "f"(lo), "f"(hi));
    return d;
}
__device__ __forceinline__ void unpack_f32x2(u64 v, float& lo, float& hi) {
    asm("mov.b64 {%0, %1}, %2;" : "=f"(lo), "=f"(hi) : "l"(v));
}

// ---------------- index dtype handling ----------------
__device__ __forceinline__ int load_idx_w(const void* p, int i, int is64) {
    if (is64) return (int)((const long long*)p)[i];
    return ((const int*)p)[i];
}

__device__ __forceinline__ int detect_is64(const void* src) {
    const unsigned long long* p = (const unsigned long long*)src;
    int lane = threadIdx.x & 31;
    int bad = (p[lane] >= (unsigned long long)N_NODES) ? 1 : 0;
    unsigned m = __ballot_sync(0xFFFFFFFFu, bad);
    return (m == 0u) ? 1 : 0;
}

// ---------------- degree count (4 edges/thread) + chunk totals ----------------
__global__ void count_deg_kernel(const void* src, const void* dst) {
    __shared__ int s_is64;
    if (threadIdx.x < 32) {
        int v = detect_is64(src);
        if (threadIdx.x == 0) {
            s_is64 = v;
            if (blockIdx.x == 0) g_is64 = v;   // for csr_fill (stream-ordered)
        }
    }
    __syncthreads();
    int is64 = s_is64;
    int t = blockIdx.x * blockDim.x + threadIdx.x;
    int e0 = t * 4;
    if (e0 >= N_EDGES) return;
    #pragma unroll
    for (int j = 0; j < 4; j++) {
        int e = e0 + j;
        if (e < N_EDGES) {
            int s = load_idx_w(src, e, is64);
            int d = load_idx_w(dst, e, is64);
            atomicAdd(&g_deg_src[s], 1);
            atomicAdd(&g_deg_dst[d], 1);
            atomicAdd(&g_blocksum[d >> 8], 1);   // chunk total (no return -> RED)
        }
    }
}

// ---------------- single scan pass: offsets/cursor + norms ----------------
// Each block handles 256 nodes. Base = sum of blocksum[t] for t < blockIdx
// (computed by a block-wide masked reduction over the 196 chunk totals).
__global__ __launch_bounds__(256) void scan_kernel() {
    __shared__ int wsum[8];
    __shared__ int bsum[8];

    int tid = threadIdx.x;
    int lane = tid & 31, wid = tid >> 5;
    int i = blockIdx.x * 256 + tid;

    // masked reduce of chunk totals -> base
    int bv = (tid < NB && tid < blockIdx.x) ? g_blocksum[tid] : 0;
    #pragma unroll
    for (int off = 16; off > 0; off >>= 1) bv += __shfl_down_sync(0xFFFFFFFFu, bv, off);
    if (lane == 0) bsum[wid] = bv;

    int v = (i < N_NODES) ? g_deg_dst[i] : 0;
    if (i < N_NODES) {
        g_norm_src[i] = rsqrtf(fmaxf((float)g_deg_src[i], 1.0f));
        g_norm_dst[i] = rsqrtf(fmaxf((float)v, 1.0f));
    }

    // block-local exclusive scan of v
    int incl = v;
    #pragma unroll
    for (int off = 1; off < 32; off <<= 1) {
        int u = __shfl_up_sync(0xFFFFFFFFu, incl, off);
        if (lane >= off) incl += u;
    }
    if (lane == 31) wsum[wid] = incl;
    __syncthreads();
    if (wid == 0 && lane < 8) {
        int w = wsum[lane];
        #pragma unroll
        for (int off = 1; off < 8; off <<= 1) {
            int u = __shfl_up_sync(0xFFu, w, off);
            if (lane >= off) w += u;
        }
        wsum[lane] = w;
        // also finish base reduction in warp 0
        int b = bsum[lane];
        #pragma unroll
        for (int off = 4; off > 0; off >>= 1) b += __shfl_down_sync(0xFFu, b, off);
        if (lane == 0) bsum[0] = b;
    }
    __syncthreads();
    int base = bsum[0];
    int excl = incl - v + (wid > 0 ? wsum[wid - 1] : 0) + base;
    if (i < N_NODES) {
        g_offsets[i] = excl;
        g_cursor[i]  = excl;
    }
    if (blockIdx.x == 0 && tid == 0) g_offsets[N_NODES] = N_EDGES;
}

// ---------------- CSR fill (4 edges/thread) ----------------
__global__ void csr_fill_kernel(const void* src, const void* dst) {
    int is64 = g_is64;
    int t = blockIdx.x * blockDim.x + threadIdx.x;
    int e0 = t * 4;
    if (e0 >= N_EDGES) return;
    int s[4], d[4];
    #pragma unroll
    for (int j = 0; j < 4; j++) {
        int e = e0 + j;
        s[j] = (e < N_EDGES) ? load_idx_w(src, e, is64) : -1;
        d[j] = (e < N_EDGES) ? load_idx_w(dst, e, is64) : -1;
    }
    #pragma unroll
    for (int j = 0; j < 4; j++) {
        if (s[j] >= 0) {
            int pos = atomicAdd(&g_cursor[d[j]], 1);
            g_csr[pos] = s[j];
        }
    }
}

// ---------------- GEMM1: g_h = fp16(x @ W1)   [50000x256]x[256x64], FFMA2 ----------------
#define BM 128
#define BK 16
#define BN 64
__global__ __launch_bounds__(256) void gemm1_kernel(const float* __restrict__ x,
                                                    const float* __restrict__ W1) {
    __shared__ float As[BK][BM + 4];
    __shared__ u64   Bs2[BK][BN];

    int row0 = blockIdx.x * BM;
    int tid = threadIdx.x;
    int tx = tid & 15;
    int ty = tid >> 4;

    u64 acc[4][4];
    #pragma unroll
    for (int p = 0; p < 4; p++)
        #pragma unroll
        for (int j = 0; j < 4; j++) acc[p][j] = 0ull;

    for (int k0 = 0; k0 < NFEAT; k0 += BK) {
        #pragma unroll
        for (int i = 0; i < 2; i++) {
            int idx = tid + i * 256;
            int r  = idx >> 2;
            int c4 = idx & 3;
            int grow = row0 + r;
            float4 vv = make_float4(0.f, 0.f, 0.f, 0.f);
            if (grow < N_NODES)
                vv = *(const float4*)(x + (size_t)grow * NFEAT + k0 + c4 * 4);
            As[c4 * 4 + 0][r] = vv.x;
            As[c4 * 4 + 1][r] = vv.y;
            As[c4 * 4 + 2][r] = vv.z;
            As[c4 * 4 + 3][r] = vv.w;
        }
        {
            int kk = tid >> 4;
            int n0 = (tid & 15) * 4;
            float4 vv = *(const float4*)(W1 + (size_t)(k0 + kk) * NHID + n0);
            Bs2[kk][n0 + 0] = pack_f32x2(vv.x, vv.x);
            Bs2[kk][n0 + 1] = pack_f32x2(vv.y, vv.y);
            Bs2[kk][n0 + 2] = pack_f32x2(vv.z, vv.z);
            Bs2[kk][n0 + 3] = pack_f32x2(vv.w, vv.w);
        }
        __syncthreads();

        #pragma unroll
        for (int kk = 0; kk < BK; kk++) {
            ulonglong2 a01 = *(const ulonglong2*)&As[kk][ty * 8];
            ulonglong2 a23 = *(const ulonglong2*)&As[kk][ty * 8 + 4];
            ulonglong2 b01 = *(const ulonglong2*)&Bs2[kk][tx * 4];
            ulonglong2 b23 = *(const ulonglong2*)&Bs2[kk][tx * 4 + 2];
            u64 a[4] = {a01.x, a01.y, a23.x, a23.y};
            u64 b[4] = {b01.x, b01.y, b23.x, b23.y};
            #pragma unroll
            for (int p = 0; p < 4; p++)
                #pragma unroll
                for (int j = 0; j < 4; j++)
                    acc[p][j] = fma_f32x2(a[p], b[j], acc[p][j]);
        }
        __syncthreads();
    }

    #pragma unroll
    for (int p = 0; p < 4; p++) {
        float lo[4], hi[4];
        #pragma unroll
        for (int j = 0; j < 4; j++) unpack_f32x2(acc[p][j], lo[j], hi[j]);
        int r0 = row0 + ty * 8 + 2 * p;
        if (r0 < N_NODES) {
            __half2 h0 = __floats2half2_rn(lo[0], lo[1]);
            __half2 h1 = __floats2half2_rn(lo[2], lo[3]);
            *(uint2*)(g_h + (size_t)r0 * NHID + tx * 4) =
                make_uint2(*(unsigned*)&h0, *(unsigned*)&h1);
        }
        if (r0 + 1 < N_NODES) {
            __half2 h0 = __floats2half2_rn(hi[0], hi[1]);
            __half2 h1 = __floats2half2_rn(hi[2], hi[3]);
            *(uint2*)(g_h + (size_t)(r0 + 1) * NHID + tx * 4) =
                make_uint2(*(unsigned*)&h0, *(unsigned*)&h1);
        }
    }
}

// ---------------- AGG1 + layer2 fused (norm_src applied per-edge) ----------------
__global__ void agg1_kernel(const float* __restrict__ b1, const float* __restrict__ W2) {
    int gw = (blockIdx.x * blockDim.x + threadIdx.x) >> 5;
    int lane = threadIdx.x & 31;
    if (gw >= N_NODES) return;
    int n = gw;
    int beg = g_offsets[n], end = g_offsets[n + 1];
    float ax = 0.f, ay = 0.f;
    int i = beg;
    for (; i + 3 < end; i += 4) {
        int s0 = g_csr[i], s1 = g_csr[i + 1], s2 = g_csr[i + 2], s3 = g_csr[i + 3];
        float n0 = g_norm_src[s0], n1 = g_norm_src[s1];
        float n2 = g_norm_src[s2], n3 = g_norm_src[s3];
        float2 v0 = __half22float2(*(const __half2*)(g_h + (size_t)s0 * NHID + lane * 2));
        float2 v1 = __half22float2(*(const __half2*)(g_h + (size_t)s1 * NHID + lane * 2));
        float2 v2 = __half22float2(*(const __half2*)(g_h + (size_t)s2 * NHID + lane * 2));
        float2 v3 = __half22float2(*(const __half2*)(g_h + (size_t)s3 * NHID + lane * 2));
        ax = fmaf(v0.x, n0, fmaf(v1.x, n1, fmaf(v2.x, n2, fmaf(v3.x, n3, ax))));
        ay = fmaf(v0.y, n0, fmaf(v1.y, n1, fmaf(v2.y, n2, fmaf(v3.y, n3, ay))));
    }
    for (; i < end; i++) {
        int s0 = g_csr[i];
        float n0 = g_norm_src[s0];
        float2 v0 = __half22float2(*(const __half2*)(g_h + (size_t)s0 * NHID + lane * 2));
        ax = fmaf(v0.x, n0, ax);
        ay = fmaf(v0.y, n0, ay);
    }
    float nd = g_norm_dst[n], ns = g_norm_src[n];
    float o0 = fmaxf(fmaf(ax, nd, __ldg(&b1[lane * 2 + 0])), 0.f) * ns;
    float o1 = fmaxf(fmaf(ay, nd, __ldg(&b1[lane * 2 + 1])), 0.f) * ns;
    float w00 = __ldg(&W2[(lane * 2 + 0) * 2 + 0]);
    float w01 = __ldg(&W2[(lane * 2 + 0) * 2 + 1]);
    float w10 = __ldg(&W2[(lane * 2 + 1) * 2 + 0]);
    float w11 = __ldg(&W2[(lane * 2 + 1) * 2 + 1]);
    float c0 = fmaf(o0, w00, o1 * w10);
    float c1 = fmaf(o0, w01, o1 * w11);
    #pragma unroll
    for (int off = 16; off > 0; off >>= 1) {
        c0 += __shfl_down_sync(0xFFFFFFFFu, c0, off);
        c1 += __shfl_down_sync(0xFFFFFFFFu, c1, off);
    }
    if (lane == 0) *(float2*)(g_h2 + (size_t)n * NCLASS) = make_float2(c0, c1);
}

// ---------------- AGG2 + log_softmax (+ re-zero deg/blocksum for next call) ----------------
__global__ void agg2_softmax_kernel(const float* __restrict__ b2, float* __restrict__ out) {
    int n = blockIdx.x * blockDim.x + threadIdx.x;
    if (n >= N_NODES) return;
    int beg = g_offsets[n], end = g_offsets[n + 1];
    float s0 = 0.f, s1 = 0.f;
    int i = beg;
    for (; i + 1 < end; i += 2) {
        int sa = g_csr[i], sb = g_csr[i + 1];
        float2 va = *(const float2*)(g_h2 + (size_t)sa * NCLASS);
        float2 vb = *(const float2*)(g_h2 + (size_t)sb * NCLASS);
        s0 += va.x + vb.x; s1 += va.y + vb.y;
    }
    if (i < end) {
        int sa = g_csr[i];
        float2 va = *(const float2*)(g_h2 + (size_t)sa * NCLASS);
        s0 += va.x; s1 += va.y;
    }
    float nd = g_norm_dst[n];
    float l0 = fmaf(s0, nd, __ldg(&b2[0]));
    float l1 = fmaf(s1, nd, __ldg(&b2[1]));
    float m = fmaxf(l0, l1);
    float lse = m + logf(expf(l0 - m) + expf(l1 - m));
    out[n * 2 + 0] = l0 - lse;
    out[n * 2 + 1] = l1 - lse;
    // reset scratch for the next (identical) call
    g_deg_src[n] = 0;
    g_deg_dst[n] = 0;
    if (n < NB) g_blocksum[n] = 0;
}

// ---------------- launch ----------------
extern "C" void kernel_launch(void* const* d_in, const int* in_sizes, int n_in,
                              void* d_out, int out_size) {
    const float* x   = (const float*)d_in[0];
    const void*  src = d_in[1];
    const void*  dst = d_in[2];
    const float* W1  = (const float*)d_in[3];
    const float* b1  = (const float*)d_in[4];
    const float* W2  = (const float*)d_in[5];
    const float* b2  = (const float*)d_in[6];
    float* out = (float*)d_out;

    static cudaStream_t s_side = nullptr;
    static cudaEvent_t ev_fork = nullptr, ev_join = nullptr;
    if (s_side == nullptr) {
        cudaStreamCreateWithFlags(&s_side, cudaStreamNonBlocking);
        cudaEventCreateWithFlags(&ev_fork, cudaEventDisableTiming);
        cudaEventCreateWithFlags(&ev_join, cudaEventDisableTiming);
    }

    // fork: GEMM (graph-independent) on side stream
    cudaEventRecord(ev_fork, 0);
    cudaStreamWaitEvent(s_side, ev_fork, 0);
    gemm1_kernel<<<(N_NODES + BM - 1) / BM, 256, 0, s_side>>>(x, W1);
    cudaEventRecord(ev_join, s_side);

    // main stream: CSR build chain (3 kernels)
    count_deg_kernel<<<(N_EDGES / 4 + 255) / 256, 256>>>(src, dst);
    scan_kernel<<<NB, 256>>>();
    csr_fill_kernel<<<(N_EDGES / 4 + 255) / 256, 256>>>(src, dst);

    // join: agg needs both CSR and g_h
    cudaStreamWaitEvent(0, ev_join, 0);
    agg1_kernel<<<(N_NODES * 32 + 255) / 256, 256>>>(b1, W2);
    agg2_softmax_kernel<<<(N_NODES + 255) / 256, 256>>>(b2, out);
}

// round 8
// speedup vs baseline: 2.4952x; 2.4952x over previous
#include <cuda_runtime.h>
#include <cuda_fp16.h>
#include <math.h>

#define N_NODES 50000
#define N_EDGES 800000
#define NFEAT 256
#define NHID 64
#define NCLASS 2
#define NB ((N_NODES + 255) / 256)   // 196 blocks of 256 nodes

typedef unsigned long long u64;

// ---------------- scratch (static device globals; no allocation) ----------------
__device__ int    g_deg_src[N_NODES];     // zero at load; re-zeroed by agg2 each call
__device__ int    g_deg_dst[N_NODES];
__device__ float  g_norm_src[N_NODES];
__device__ float  g_norm_dst[N_NODES];
__device__ int    g_blocksum[NB];         // per-block in-degree totals (from scanA reduce)
__device__ int    g_offsets[N_NODES + 1];
__device__ int    g_cursor[N_NODES];
__device__ int    g_csr[N_EDGES];          // src node id, bucketed by dst
__device__ __half g_h [N_NODES * NHID];    // x @ W1 (unscaled), fp16
__device__ float  g_h2[N_NODES * NCLASS];  // per-node layer2 logits (pre-agg)
__device__ int    g_is64;

// ---------------- packed f32x2 helpers ----------------
__device__ __forceinline__ u64 fma_f32x2(u64 a, u64 b, u64 c) {
    u64 d;
    asm("fma.rn.f32x2 %0, %1, %2, %3;" : "=l"(d) : "l"(a), "l"(b), "l"(c));
    return d;
}
__device__ __forceinline__ u64 pack_f32x2(float lo, float hi) {
    u64 d;
    asm("mov.b64 %0, {%1, %2};" : "=l"(d) : "f"(lo), "f"(hi));
    return d;
}
__device__ __forceinline__ void unpack_f32x2(u64 v, float& lo, float& hi) {
    asm("mov.b64 {%0, %1}, %2;" : "=f"(lo), "=f"(hi) : "l"(v));
}

// ---------------- index dtype handling ----------------
__device__ __forceinline__ int load_idx_w(const void* p, int i, int is64) {
    if (is64) return (int)((const long long*)p)[i];
    return ((const int*)p)[i];
}

__device__ __forceinline__ int detect_is64(const void* src) {
    const unsigned long long* p = (const unsigned long long*)src;
    int lane = threadIdx.x & 31;
    int bad = (p[lane] >= (unsigned long long)N_NODES) ? 1 : 0;
    unsigned m = __ballot_sync(0xFFFFFFFFu, bad);
    return (m == 0u) ? 1 : 0;
}

// ---------------- degree count (8 edges/thread) ----------------
__global__ void count_deg_kernel(const void* src, const void* dst) {
    __shared__ int s_is64;
    if (threadIdx.x < 32) {
        int v = detect_is64(src);
        if (threadIdx.x == 0) {
            s_is64 = v;
            if (blockIdx.x == 0) g_is64 = v;   // for csr_fill (stream-ordered)
        }
    }
    __syncthreads();
    int is64 = s_is64;
    int t = blockIdx.x * blockDim.x + threadIdx.x;
    int e0 = t * 8;
    if (e0 >= N_EDGES) return;
    #pragma unroll
    for (int j = 0; j < 8; j++) {
        int e = e0 + j;
        if (e < N_EDGES) {
            atomicAdd(&g_deg_src[load_idx_w(src, e, is64)], 1);
            atomicAdd(&g_deg_dst[load_idx_w(dst, e, is64)], 1);
        }
    }
}

// ---------------- scanA: per-block reduce of deg_dst -> blocksum (+ norms) ----------------
__global__ __launch_bounds__(256) void scanA_kernel() {
    __shared__ int wsum[8];
    int i = blockIdx.x * 256 + threadIdx.x;
    int v = (i < N_NODES) ? g_deg_dst[i] : 0;
    if (i < N_NODES) {
        g_norm_src[i] = rsqrtf(fmaxf((float)g_deg_src[i], 1.0f));
        g_norm_dst[i] = rsqrtf(fmaxf((float)v, 1.0f));
    }
    int lane = threadIdx.x & 31, wid = threadIdx.x >> 5;
    int s = v;
    #pragma unroll
    for (int off = 16; off > 0; off >>= 1) s += __shfl_down_sync(0xFFFFFFFFu, s, off);
    if (lane == 0) wsum[wid] = s;
    __syncthreads();
    if (threadIdx.x == 0) {
        int t = 0;
        #pragma unroll
        for (int w = 0; w < 8; w++) t += wsum[w];
        g_blocksum[blockIdx.x] = t;
    }
}

// ---------------- scanC: base = masked-reduce(blocksum) ; local scan -> offsets ----------------
__global__ __launch_bounds__(256) void scanC_kernel() {
    __shared__ int wsum[8];
    __shared__ int bsum[8];

    int tid = threadIdx.x;
    int lane = tid & 31, wid = tid >> 5;
    int i = blockIdx.x * 256 + tid;

    // base: sum of blocksum[t] for t < blockIdx.x (NB=196 < 256 -> one load/thread)
    int bv = (tid < NB && tid < blockIdx.x) ? g_blocksum[tid] : 0;
    #pragma unroll
    for (int off = 16; off > 0; off >>= 1) bv += __shfl_down_sync(0xFFFFFFFFu, bv, off);
    if (lane == 0) bsum[wid] = bv;

    int v = (i < N_NODES) ? g_deg_dst[i] : 0;

    // block-local exclusive scan
    int incl = v;
    #pragma unroll
    for (int off = 1; off < 32; off <<= 1) {
        int u = __shfl_up_sync(0xFFFFFFFFu, incl, off);
        if (lane >= off) incl += u;
    }
    if (lane == 31) wsum[wid] = incl;
    __syncthreads();
    if (wid == 0 && lane < 8) {
        int w = wsum[lane];
        #pragma unroll
        for (int off = 1; off < 8; off <<= 1) {
            int u = __shfl_up_sync(0xFFu, w, off);
            if (lane >= off) w += u;
        }
        wsum[lane] = w;
        int b = bsum[lane];
        #pragma unroll
        for (int off = 4; off > 0; off >>= 1) b += __shfl_down_sync(0xFFu, b, off);
        if (lane == 0) bsum[0] = b;
    }
    __syncthreads();
    int excl = incl - v + (wid > 0 ? wsum[wid - 1] : 0) + bsum[0];
    if (i < N_NODES) {
        g_offsets[i] = excl;
        g_cursor[i]  = excl;
    }
    if (blockIdx.x == 0 && tid == 0) g_offsets[N_NODES] = N_EDGES;
}

// ---------------- CSR fill (8 edges/thread) ----------------
__global__ void csr_fill_kernel(const void* src, const void* dst) {
    int is64 = g_is64;
    int t = blockIdx.x * blockDim.x + threadIdx.x;
    int e0 = t * 8;
    if (e0 >= N_EDGES) return;
    int s[8], d[8];
    #pragma unroll
    for (int j = 0; j < 8; j++) {
        int e = e0 + j;
        s[j] = (e < N_EDGES) ? load_idx_w(src, e, is64) : -1;
        d[j] = (e < N_EDGES) ? load_idx_w(dst, e, is64) : -1;
    }
    #pragma unroll
    for (int j = 0; j < 8; j++) {
        if (s[j] >= 0) {
            int pos = atomicAdd(&g_cursor[d[j]], 1);
            g_csr[pos] = s[j];
        }
    }
}

// ---------------- GEMM1: g_h = fp16(x @ W1)   [50000x256]x[256x64], FFMA2 ----------------
#define BM 128
#define BK 16
#define BN 64
__global__ __launch_bounds__(256) void gemm1_kernel(const float* __restrict__ x,
                                                    const float* __restrict__ W1) {
    __shared__ float As[BK][BM + 4];
    __shared__ u64   Bs2[BK][BN];

    int row0 = blockIdx.x * BM;
    int tid = threadIdx.x;
    int tx = tid & 15;
    int ty = tid >> 4;

    u64 acc[4][4];
    #pragma unroll
    for (int p = 0; p < 4; p++)
        #pragma unroll
        for (int j = 0; j < 4; j++) acc[p][j] = 0ull;

    for (int k0 = 0; k0 < NFEAT; k0 += BK) {
        #pragma unroll
        for (int i = 0; i < 2; i++) {
            int idx = tid + i * 256;
            int r  = idx >> 2;
            int c4 = idx & 3;
            int grow = row0 + r;
            float4 vv = make_float4(0.f, 0.f, 0.f, 0.f);
            if (grow < N_NODES)
                vv = *(const float4*)(x + (size_t)grow * NFEAT + k0 + c4 * 4);
            As[c4 * 4 + 0][r] = vv.x;
            As[c4 * 4 + 1][r] = vv.y;
            As[c4 * 4 + 2][r] = vv.z;
            As[c4 * 4 + 3][r] = vv.w;
        }
        {
            int kk = tid >> 4;
            int n0 = (tid & 15) * 4;
            float4 vv = *(const float4*)(W1 + (size_t)(k0 + kk) * NHID + n0);
            Bs2[kk][n0 + 0] = pack_f32x2(vv.x, vv.x);
            Bs2[kk][n0 + 1] = pack_f32x2(vv.y, vv.y);
            Bs2[kk][n0 + 2] = pack_f32x2(vv.z, vv.z);
            Bs2[kk][n0 + 3] = pack_f32x2(vv.w, vv.w);
        }
        __syncthreads();

        #pragma unroll
        for (int kk = 0; kk < BK; kk++) {
            ulonglong2 a01 = *(const ulonglong2*)&As[kk][ty * 8];
            ulonglong2 a23 = *(const ulonglong2*)&As[kk][ty * 8 + 4];
            ulonglong2 b01 = *(const ulonglong2*)&Bs2[kk][tx * 4];
            ulonglong2 b23 = *(const ulonglong2*)&Bs2[kk][tx * 4 + 2];
            u64 a[4] = {a01.x, a01.y, a23.x, a23.y};
            u64 b[4] = {b01.x, b01.y, b23.x, b23.y};
            #pragma unroll
            for (int p = 0; p < 4; p++)
                #pragma unroll
                for (int j = 0; j < 4; j++)
                    acc[p][j] = fma_f32x2(a[p], b[j], acc[p][j]);
        }
        __syncthreads();
    }

    #pragma unroll
    for (int p = 0; p < 4; p++) {
        float lo[4], hi[4];
        #pragma unroll
        for (int j = 0; j < 4; j++) unpack_f32x2(acc[p][j], lo[j], hi[j]);
        int r0 = row0 + ty * 8 + 2 * p;
        if (r0 < N_NODES) {
            __half2 h0 = __floats2half2_rn(lo[0], lo[1]);
            __half2 h1 = __floats2half2_rn(lo[2], lo[3]);
            *(uint2*)(g_h + (size_t)r0 * NHID + tx * 4) =
                make_uint2(*(unsigned*)&h0, *(unsigned*)&h1);
        }
        if (r0 + 1 < N_NODES) {
            __half2 h0 = __floats2half2_rn(hi[0], hi[1]);
            __half2 h1 = __floats2half2_rn(hi[2], hi[3]);
            *(uint2*)(g_h + (size_t)(r0 + 1) * NHID + tx * 4) =
                make_uint2(*(unsigned*)&h0, *(unsigned*)&h1);
        }
    }
}

// ---------------- AGG1 + layer2 fused (norm_src applied per-edge) ----------------
__global__ void agg1_kernel(const float* __restrict__ b1, const float* __restrict__ W2) {
    int gw = (blockIdx.x * blockDim.x + threadIdx.x) >> 5;
    int lane = threadIdx.x & 31;
    if (gw >= N_NODES) return;
    int n = gw;
    int beg = g_offsets[n], end = g_offsets[n + 1];
    float ax = 0.f, ay = 0.f;
    int i = beg;
    for (; i + 3 < end; i += 4) {
        int s0 = g_csr[i], s1 = g_csr[i + 1], s2 = g_csr[i + 2], s3 = g_csr[i + 3];
        float n0 = g_norm_src[s0], n1 = g_norm_src[s1];
        float n2 = g_norm_src[s2], n3 = g_norm_src[s3];
        float2 v0 = __half22float2(*(const __half2*)(g_h + (size_t)s0 * NHID + lane * 2));
        float2 v1 = __half22float2(*(const __half2*)(g_h + (size_t)s1 * NHID + lane * 2));
        float2 v2 = __half22float2(*(const __half2*)(g_h + (size_t)s2 * NHID + lane * 2));
        float2 v3 = __half22float2(*(const __half2*)(g_h + (size_t)s3 * NHID + lane * 2));
        ax = fmaf(v0.x, n0, fmaf(v1.x, n1, fmaf(v2.x, n2, fmaf(v3.x, n3, ax))));
        ay = fmaf(v0.y, n0, fmaf(v1.y, n1, fmaf(v2.y, n2, fmaf(v3.y, n3, ay))));
    }
    for (; i < end; i++) {
        int s0 = g_csr[i];
        float n0 = g_norm_src[s0];
        float2 v0 = __half22float2(*(const __half2*)(g_h + (size_t)s0 * NHID + lane * 2));
        ax = fmaf(v0.x, n0, ax);
        ay = fmaf(v0.y, n0, ay);
    }
    float nd = g_norm_dst[n], ns = g_norm_src[n];
    float o0 = fmaxf(fmaf(ax, nd, __ldg(&b1[lane * 2 + 0])), 0.f) * ns;
    float o1 = fmaxf(fmaf(ay, nd, __ldg(&b1[lane * 2 + 1])), 0.f) * ns;
    float w00 = __ldg(&W2[(lane * 2 + 0) * 2 + 0]);
    float w01 = __ldg(&W2[(lane * 2 + 0) * 2 + 1]);
    float w10 = __ldg(&W2[(lane * 2 + 1) * 2 + 0]);
    float w11 = __ldg(&W2[(lane * 2 + 1) * 2 + 1]);
    float c0 = fmaf(o0, w00, o1 * w10);
    float c1 = fmaf(o0, w01, o1 * w11);
    #pragma unroll
    for (int off = 16; off > 0; off >>= 1) {
        c0 += __shfl_down_sync(0xFFFFFFFFu, c0, off);
        c1 += __shfl_down_sync(0xFFFFFFFFu, c1, off);
    }
    if (lane == 0) *(float2*)(g_h2 + (size_t)n * NCLASS) = make_float2(c0, c1);
}

// ---------------- AGG2 + log_softmax (+ re-zero degrees for next call) ----------------
__global__ void agg2_softmax_kernel(const float* __restrict__ b2, float* __restrict__ out) {
    int n = blockIdx.x * blockDim.x + threadIdx.x;
    if (n >= N_NODES) return;
    int beg = g_offsets[n], end = g_offsets[n + 1];
    float s0 = 0.f, s1 = 0.f;
    int i = beg;
    for (; i + 1 < end; i += 2) {
        int sa = g_csr[i], sb = g_csr[i + 1];
        float2 va = *(const float2*)(g_h2 + (size_t)sa * NCLASS);
        float2 vb = *(const float2*)(g_h2 + (size_t)sb * NCLASS);
        s0 += va.x + vb.x; s1 += va.y + vb.y;
    }
    if (i < end) {
        int sa = g_csr[i];
        float2 va = *(const float2*)(g_h2 + (size_t)sa * NCLASS);
        s0 += va.x; s1 += va.y;
    }
    float nd = g_norm_dst[n];
    float l0 = fmaf(s0, nd, __ldg(&b2[0]));
    float l1 = fmaf(s1, nd, __ldg(&b2[1]));
    float m = fmaxf(l0, l1);
    float lse = m + logf(expf(l0 - m) + expf(l1 - m));
    out[n * 2 + 0] = l0 - lse;
    out[n * 2 + 1] = l1 - lse;
    // reset scratch for the next (identical) call
    g_deg_src[n] = 0;
    g_deg_dst[n] = 0;
}

// ---------------- launch ----------------
extern "C" void kernel_launch(void* const* d_in, const int* in_sizes, int n_in,
                              void* d_out, int out_size) {
    const float* x   = (const float*)d_in[0];
    const void*  src = d_in[1];
    const void*  dst = d_in[2];
    const float* W1  = (const float*)d_in[3];
    const float* b1  = (const float*)d_in[4];
    const float* W2  = (const float*)d_in[5];
    const float* b2  = (const float*)d_in[6];
    float* out = (float*)d_out;

    static cudaStream_t s_side = nullptr;
    static cudaEvent_t ev_fork = nullptr, ev_join = nullptr;
    if (s_side == nullptr) {
        cudaStreamCreateWithFlags(&s_side, cudaStreamNonBlocking);
        cudaEventCreateWithFlags(&ev_fork, cudaEventDisableTiming);
        cudaEventCreateWithFlags(&ev_join, cudaEventDisableTiming);
    }

    // fork: GEMM (graph-independent) on side stream
    cudaEventRecord(ev_fork, 0);
    cudaStreamWaitEvent(s_side, ev_fork, 0);
    gemm1_kernel<<<(N_NODES + BM - 1) / BM, 256, 0, s_side>>>(x, W1);
    cudaEventRecord(ev_join, s_side);

    // main stream: CSR build chain (4 kernels)
    count_deg_kernel<<<(N_EDGES / 8 + 255) / 256, 256>>>(src, dst);
    scanA_kernel<<<NB, 256>>>();
    scanC_kernel<<<NB, 256>>>();
    csr_fill_kernel<<<(N_EDGES / 8 + 255) / 256, 256>>>(src, dst);

    // join: agg needs both CSR and g_h
    cudaStreamWaitEvent(0, ev_join, 0);
    agg1_kernel<<<(N_NODES * 32 + 255) / 256, 256>>>(b1, W2);
    agg2_softmax_kernel<<<(N_NODES + 255) / 256, 256>>>(b2, out);
}